// round 12
// baseline (speedup 1.0000x reference)
#include <cuda_runtime.h>
#include <cuda_fp16.h>
#include <math.h>
#include <stdint.h>

// ---------------------------------------------------------------------------
// ConvLSTM (2 layers, 12 steps) — tensor-core implicit GEMM, pure fp16.
// R12: (a) 512-thr blocks (8 warps/SMSP at 2 blocks/SM) now that weights are
//      direct-LDG (smem only 46.6KB) -> better HMMA latency hiding;
//      (b) L1 runs on a side stream overlapped with next-step L0 (event
//      fork/join; h0 buffer reuse guarded by L1(t) -> L0(t+2) edges).
// Weights LDG.128'd straight from frag-ordered global (L1-hot, no smem stage).
// Activations stored as channel-pair planes: uint32 = {fp16 ch2p | fp16 ch2p+1}.
// ---------------------------------------------------------------------------

#define TSTEPS 12
#define NCHUNK 9

__device__ uint32_t g_h0p[2u * 16u * 64u * 4096u];   // h0 pair planes (fp16x2)
__device__ uint32_t g_h1p[2u * 16u * 6u  * 4096u];   // h1 pair planes
__device__ uint32_t g_xp [12u * 16u * 4096u];        // x pair planes per t
__device__ float    g_c0 [16u * 128u * 4096u];
__device__ float    g_c1 [16u * 12u  * 4096u];
__device__ float    g_h1f[16u * 12u * 4096u];        // float h1 (output, t=11)
__device__ uint32_t g_wp0[8u * 9u * 4608u];          // frag-packed fp16 weights
__device__ uint32_t g_wp1[1u * 9u * 4608u];

#define SW_ACT   5824u              // one act chunk: 8 planes * 728 words
#define SMEM_BYTES (2u * SW_ACT * 4u)        // 46,592 B -> 2 blocks/SM @512thr

// -------------------- helpers ----------------------------------------------
__device__ __forceinline__ void mma_f16(float* d, const uint32_t* a,
                                        uint32_t b0, uint32_t b1) {
    asm volatile(
        "mma.sync.aligned.m16n8k16.row.col.f32.f16.f16.f32 "
        "{%0,%1,%2,%3}, {%4,%5,%6,%7}, {%8,%9}, {%0,%1,%2,%3};"
        : "+f"(d[0]), "+f"(d[1]), "+f"(d[2]), "+f"(d[3])
        : "r"(a[0]), "r"(a[1]), "r"(a[2]), "r"(a[3]), "r"(b0), "r"(b1));
}
__device__ __forceinline__ uint32_t smaddr(const void* p) {
    return (uint32_t)__cvta_generic_to_shared(p);
}
__device__ __forceinline__ void cpa16(uint32_t dst, const void* src) {
    asm volatile("cp.async.cg.shared.global [%0], [%1], 16;" :: "r"(dst), "l"(src));
}
__device__ __forceinline__ uint32_t pack_hf(float a, float b) {
    __half2 h = __floats2half2_rn(a, b);
    return *(uint32_t*)&h;
}
__device__ __forceinline__ float ex2f(float x) {
    float y; asm("ex2.approx.f32 %0, %1;" : "=f"(y) : "f"(x)); return y;
}
__device__ __forceinline__ float rcpf(float x) {
    float y; asm("rcp.approx.f32 %0, %1;" : "=f"(y) : "f"(x)); return y;
}
__device__ __forceinline__ float sigf(float x) {
    return rcpf(1.f + ex2f(-1.44269504f * x));
}
__device__ __forceinline__ float tanh_fast(float x) {
    return 2.f * rcpf(1.f + ex2f(-2.88539008f * x)) - 1.f;
}

// -------------------- init kernels -----------------------------------------
__global__ void zero_init_kernel() {
    size_t tid = (size_t)blockIdx.x * blockDim.x + threadIdx.x;
    size_t st  = (size_t)gridDim.x * blockDim.x;
    const size_t nh0 = (size_t)2 * 16 * 64 * 4096;
    const size_t nh1 = (size_t)2 * 16 * 6 * 4096;
    const size_t nc0 = (size_t)16 * 128 * 4096;
    const size_t nc1 = (size_t)16 * 12 * 4096;
    for (size_t i = tid; i < nh0; i += st) g_h0p[i] = 0u;
    for (size_t i = tid; i < nh1; i += st) g_h1p[i] = 0u;
    for (size_t i = tid; i < nc0; i += st) g_c0[i] = 0.f;
    for (size_t i = tid; i < nc1; i += st) g_c1[i] = 0.f;
}

__global__ void xprep_kernel(const float* __restrict__ hist) {
    int n = TSTEPS * 16 * 4096;
    for (int i = blockIdx.x * blockDim.x + threadIdx.x; i < n;
         i += gridDim.x * blockDim.x) {
        int px = i & 4095, b = (i >> 12) & 15, t = i >> 16;
        float v = hist[((size_t)b * TSTEPS + t) * 4096 + px];
        g_xp[((size_t)t * 16 + b) * 4096 + px] = pack_hf(v, 0.f);
    }
}

// Weights -> A-fragment order: [hb][chunk][ (tap*4+g)*128 + lane*4 + r ]
// reg r: m = lane/4 + (r&1)*8 ; pair = lane%4 + ((r>>1)&1)*4
__global__ void repack_w(const float* __restrict__ W, uint32_t* __restrict__ Wp,
                         int HID, int CIN, int NHB, int layer) {
    int total = NHB * NCHUNK * 4608;
    for (int idx = blockIdx.x * blockDim.x + threadIdx.x; idx < total;
         idx += gridDim.x * blockDim.x) {
        int wrd = idx % 4608, rest = idx / 4608;
        int c = rest % NCHUNK, hb = rest / NCHUNK;
        int r = wrd & 3, lane = (wrd >> 2) & 31, gt = wrd >> 7;
        int g = gt & 3, t = gt >> 2;
        int m  = (lane >> 2) + (r & 1) * 8;
        int pr = (lane & 3) + ((r >> 1) & 1) * 4;
        int p  = c * 8 + pr;
        int hid = hb * 16 + m;
        int k0 = -1, k1 = -1;
        if (layer == 0) {
            if (p < 64)       { k0 = 2 * p + 1; k1 = 2 * p + 2; }
            else if (p == 64) { k0 = 0; }
        } else {
            if (p < 64)      { k0 = 2 * p; k1 = 2 * p + 1; }
            else if (p < 70) { k0 = 128 + 2 * (p - 64); k1 = k0 + 1; }
        }
        float w0 = 0.f, w1 = 0.f;
        if (hid < HID) {
            if (k0 >= 0) w0 = W[((size_t)(g * HID + hid) * CIN + k0) * 9 + t];
            if (k1 >= 0) w1 = W[((size_t)(g * HID + hid) * CIN + k1) * 9 + t];
        }
        Wp[idx] = pack_hf(w0, w1);
    }
}

// -------------------- fused conv + LSTM step --------------------------------
// Grid (8 y-tiles, NHB, 16 batch), block 512 = 16 warps (wx 0..7, wy 0..1).
// Warp: 16 hid x 4 gates x 32 px (8-px strip, 4 rows). 64 f32 accs/thread.
// Weights: per-tap LDG.128 fragments straight from global (L1-cached).
template <int NPA, int NPB, int HID>
__global__ __launch_bounds__(512, 2)
void conv_step(const uint32_t* __restrict__ actA,   // [b][NPA][4096]
               const uint32_t* __restrict__ actB,   // [b][NPB][4096]
               const uint32_t* __restrict__ Wg,     // [hb][9][4608] frag order
               const float*    __restrict__ bias,
               float*          __restrict__ cbuf,   // [b][HID][4096]
               uint32_t*       __restrict__ hout,   // [b][HID/2][4096]
               float*          __restrict__ hfout) {
    extern __shared__ uint32_t sm[];
    const int tid = threadIdx.x;
    const int lane = tid & 31, warp = tid >> 5;
    const int tg = lane & 3, gq = lane >> 2;
    const int wx = warp & 7, wy = warp >> 3;
    const int y0 = blockIdx.x * 8;
    const int hb = blockIdx.y;
    const int b  = blockIdx.z;
    const uint32_t* wgm = Wg + (size_t)hb * NCHUNK * 4608 + lane * 4;

    // zero halo columns (words 0..3 / 68..71): 2 bufs x 8 planes x 10 rows x 2
    if (tid < 320) {
        int side = tid & 1, v = tid >> 1;          // v 0..159
        int r = v % 10, p = (v / 10) & 7, bfi = v / 80;
        uint32_t* dst = sm + bfi * SW_ACT + p * 728 + r * 72 + (side ? 68 : 0);
        *(uint4*)dst = make_uint4(0, 0, 0, 0);
    }

    float acc[4][4][4];
#pragma unroll
    for (int g = 0; g < 4; g++)
#pragma unroll
        for (int n = 0; n < 4; n++)
#pragma unroll
            for (int r = 0; r < 4; r++) acc[g][n][r] = 0.f;

    auto ldchunk = [&](int c, int bfi) {
#pragma unroll
        for (int k = 0; k < 3; k++) {
            int u = tid + k * 512;               // 1280 uint4: act data
            if (u < 1280) {
                int p = u & 7, rest = u >> 3;    // rest 0..159
                int r = rest % 10, seg = rest / 10;     // seg: 16 x 4px
                int pair = c * 8 + p;
                int y = y0 + r - 1;
                uint32_t* dst = sm + bfi * SW_ACT + p * 728 + r * 72 + 4 + seg * 4;
                const uint32_t* src = nullptr;
                if ((unsigned)y < 64u) {
                    if (pair < NPA)
                        src = actA + ((size_t)b * NPA + pair) * 4096 + y * 64 + seg * 4;
                    else if (pair < NPA + NPB)
                        src = actB + ((size_t)b * NPB + (pair - NPA)) * 4096 +
                              y * 64 + seg * 4;
                }
                if (src) cpa16(smaddr(dst), src);
                else     *(uint4*)dst = make_uint4(0, 0, 0, 0);
            }
        }
        asm volatile("cp.async.commit_group;");
    };

    ldchunk(0, 0);

    for (int c = 0; c < NCHUNK; c++) {
        const int bfi = c & 1;
        if (c + 1 < NCHUNK) {
            ldchunk(c + 1, bfi ^ 1);
            asm volatile("cp.async.wait_group 1;");
        } else {
            asm volatile("cp.async.wait_group 0;");
        }
        __syncthreads();

        const uint32_t* aB = sm + bfi * SW_ACT;
        const uint32_t* wc = wgm + (size_t)c * 4608;

#pragma unroll
        for (int ky = 0; ky < 3; ky++) {
#pragma unroll
            for (int kx = 0; kx < 3; kx++) {
                const int t = ky * 3 + kx;
                const int cb = 4 + wx * 8 + gq + kx - 1;
                // stage weight fragments for this tap (4 x LDG.128, L1-hot)
                uint4 ah[4];
#pragma unroll
                for (int g = 0; g < 4; g++)
                    ah[g] = __ldg((const uint4*)(wc + (t * 4 + g) * 128));
                uint32_t bh[4][2];
#pragma unroll
                for (int nt = 0; nt < 4; nt++) {
                    int o0 = tg * 728 + (wy * 4 + ky + nt) * 72 + cb;
                    bh[nt][0] = aB[o0]; bh[nt][1] = aB[o0 + 4 * 728];
                }
#pragma unroll
                for (int g = 0; g < 4; g++) {
#pragma unroll
                    for (int nt = 0; nt < 4; nt++)
                        mma_f16(acc[g][nt], (const uint32_t*)&ah[g],
                                bh[nt][0], bh[nt][1]);
                }
            }
        }
        __syncthreads();
    }

    // ---- LSTM epilogue -----------------------------------------------------
    const int xpx = wx * 8 + tg * 2;
#pragma unroll
    for (int part = 0; part < 2; part++) {
        const int hid = hb * 16 + gq + part * 8;
        const bool hv = (hid < HID);
        float bi = 0.f, bfv = 0.f, bo = 0.f, bg = 0.f;
        if (hv) {
            bi = bias[hid]; bfv = bias[HID + hid];
            bo = bias[2 * HID + hid]; bg = bias[3 * HID + hid];
        }
#pragma unroll
        for (int nt = 0; nt < 4; nt++) {
            const int y = y0 + wy * 4 + nt;
            const size_t coff =
                ((size_t)(b * HID + (hv ? hid : 0))) * 4096 + (size_t)y * 64 + xpx;
            float2 c2 = hv ? *(const float2*)(cbuf + coff) : make_float2(0.f, 0.f);
            float cold[2] = {c2.x, c2.y}, hn[2];
#pragma unroll
            for (int q = 0; q < 2; q++) {
                float I = sigf(acc[0][nt][part * 2 + q] + bi);
                float F = sigf(acc[1][nt][part * 2 + q] + bfv);
                float O = sigf(acc[2][nt][part * 2 + q] + bo);
                float G = tanh_fast(acc[3][nt][part * 2 + q] + bg);
                float cn = F * cold[q] + I * G;
                cold[q] = cn;
                hn[q] = O * tanh_fast(cn);
            }
            if (hv) {
                *(float2*)(cbuf + coff) = make_float2(cold[0], cold[1]);
                if (hfout)
                    *(float2*)(hfout + coff) = make_float2(hn[0], hn[1]);
            }
            // pack channel pairs: partner hid^1 lives at lane^4
            float pn0 = __shfl_xor_sync(0xffffffffu, hn[0], 4);
            float pn1 = __shfl_xor_sync(0xffffffffu, hn[1], 4);
            if (((gq & 1) == 0) && hv) {
                const int qp = hid >> 1;
                const size_t ob =
                    ((size_t)b * (HID / 2) + qp) * 4096 + (size_t)y * 64 + xpx;
                *(uint2*)(hout + ob) =
                    make_uint2(pack_hf(hn[0], pn0), pack_hf(hn[1], pn1));
            }
        }
    }
}

// -------------------- host driver -------------------------------------------
extern "C" void kernel_launch(void* const* d_in, const int* in_sizes, int n_in,
                              void* d_out, int out_size) {
    (void)in_sizes; (void)n_in; (void)out_size;
    const float* history = (const float*)d_in[0];
    const float* W0 = (const float*)d_in[2];
    const float* b0 = (const float*)d_in[3];
    const float* W1 = (const float*)d_in[4];
    const float* b1 = (const float*)d_in[5];

    uint32_t *h0p, *h1p, *xp, *wp0, *wp1;
    float *c0, *c1, *h1f;
    cudaGetSymbolAddress((void**)&h0p, g_h0p);
    cudaGetSymbolAddress((void**)&h1p, g_h1p);
    cudaGetSymbolAddress((void**)&xp,  g_xp);
    cudaGetSymbolAddress((void**)&wp0, g_wp0);
    cudaGetSymbolAddress((void**)&wp1, g_wp1);
    cudaGetSymbolAddress((void**)&c0,  g_c0);
    cudaGetSymbolAddress((void**)&c1,  g_c1);
    cudaGetSymbolAddress((void**)&h1f, g_h1f);

    // lazily-created side stream + events (resources only; work is identical
    // and deterministic on every call)
    static cudaStream_t s2 = nullptr;
    static cudaEvent_t evP = nullptr, ev0[TSTEPS], ev1[TSTEPS];
    if (s2 == nullptr) {
        cudaStreamCreateWithFlags(&s2, cudaStreamNonBlocking);
        cudaEventCreateWithFlags(&evP, cudaEventDisableTiming);
        for (int t = 0; t < TSTEPS; t++) {
            cudaEventCreateWithFlags(&ev0[t], cudaEventDisableTiming);
            cudaEventCreateWithFlags(&ev1[t], cudaEventDisableTiming);
        }
    }

    zero_init_kernel<<<1024, 256>>>();
    xprep_kernel<<<768, 256>>>(history);
    repack_w<<<324, 256>>>(W0, wp0, 128, 129, 8, 0);
    repack_w<<<41, 256>>>(W1, wp1, 12, 140, 1, 1);
    cudaEventRecord(evP, 0);
    cudaStreamWaitEvent(s2, evP, 0);

    const size_t H0SZ = (size_t)16 * 64 * 4096;
    const size_t H1SZ = (size_t)16 * 6 * 4096;

    int pa = 0;
    for (int t = 0; t < TSTEPS; t++) {
        const uint32_t* h0r = h0p + (size_t)pa * H0SZ;
        uint32_t*       h0w = h0p + (size_t)(1 - pa) * H0SZ;
        const uint32_t* h1r = h1p + (size_t)pa * H1SZ;
        uint32_t*       h1w = h1p + (size_t)(1 - pa) * H1SZ;

        // L0(t) overwrites h0 buffer 'pa' ... which L1(t-2) read: guard.
        if (t >= 2) cudaStreamWaitEvent(0, ev1[t - 2], 0);

        conv_step<64, 1, 128><<<dim3(8, 8, 16), 512, SMEM_BYTES>>>(
            h0r, xp + (size_t)t * 16 * 4096, wp0, b0, c0, h0w, nullptr);
        cudaEventRecord(ev0[t], 0);

        // L1(t) on side stream: depends only on L0(t) + L1(t-1); overlaps L0(t+1)
        cudaStreamWaitEvent(s2, ev0[t], 0);
        conv_step<64, 6, 12><<<dim3(8, 1, 16), 512, SMEM_BYTES, s2>>>(
            h0w, h1r, wp1, b1, c1, h1w, (t == TSTEPS - 1) ? h1f : nullptr);
        cudaEventRecord(ev1[t], s2);

        pa ^= 1;
    }

    cudaStreamWaitEvent(0, ev1[TSTEPS - 1], 0);
    cudaMemcpyAsync(d_out, h1f, (size_t)16 * 12 * 4096 * sizeof(float),
                    cudaMemcpyDeviceToDevice);
}

// round 13
// speedup vs baseline: 5.8827x; 5.8827x over previous
#include <cuda_runtime.h>
#include <cuda_fp16.h>
#include <math.h>
#include <stdint.h>

// ---------------------------------------------------------------------------
// ConvLSTM (2 layers, 12 steps) — tensor-core implicit GEMM, pure fp16.
// R13: conv_step reverted to R11 exactly (256-thr blocks, 2/SM, 128 regs —
//      512 thr/SM is the RF ceiling with 64 f32 accs/thread).
//      Kept from R12 only: L1 on a side stream, overlapped with L0(t+1).
// Weights LDG.128'd straight from frag-ordered global (L1-hot, no smem stage).
// Activations stored as channel-pair planes: uint32 = {fp16 ch2p | fp16 ch2p+1}.
// ---------------------------------------------------------------------------

#define TSTEPS 12
#define NCHUNK 9

__device__ uint32_t g_h0p[2u * 16u * 64u * 4096u];   // h0 pair planes (fp16x2)
__device__ uint32_t g_h1p[2u * 16u * 6u  * 4096u];   // h1 pair planes
__device__ uint32_t g_xp [12u * 16u * 4096u];        // x pair planes per t
__device__ float    g_c0 [16u * 128u * 4096u];
__device__ float    g_c1 [16u * 12u  * 4096u];
__device__ float    g_h1f[16u * 12u * 4096u];        // float h1 (output, t=11)
__device__ uint32_t g_wp0[8u * 9u * 4608u];          // frag-packed fp16 weights
__device__ uint32_t g_wp1[1u * 9u * 4608u];

#define SW_ACT   3520u              // one act chunk: 8 planes * 440 words
#define SMEM_BYTES (2u * SW_ACT * 4u)        // 28,160 B

// -------------------- helpers ----------------------------------------------
__device__ __forceinline__ void mma_f16(float* d, const uint32_t* a,
                                        uint32_t b0, uint32_t b1) {
    asm volatile(
        "mma.sync.aligned.m16n8k16.row.col.f32.f16.f16.f32 "
        "{%0,%1,%2,%3}, {%4,%5,%6,%7}, {%8,%9}, {%0,%1,%2,%3};"
        : "+f"(d[0]), "+f"(d[1]), "+f"(d[2]), "+f"(d[3])
        : "r"(a[0]), "r"(a[1]), "r"(a[2]), "r"(a[3]), "r"(b0), "r"(b1));
}
__device__ __forceinline__ uint32_t smaddr(const void* p) {
    return (uint32_t)__cvta_generic_to_shared(p);
}
__device__ __forceinline__ void cpa16(uint32_t dst, const void* src) {
    asm volatile("cp.async.cg.shared.global [%0], [%1], 16;" :: "r"(dst), "l"(src));
}
__device__ __forceinline__ uint32_t pack_hf(float a, float b) {
    __half2 h = __floats2half2_rn(a, b);
    return *(uint32_t*)&h;
}
__device__ __forceinline__ float ex2f(float x) {
    float y; asm("ex2.approx.f32 %0, %1;" : "=f"(y) : "f"(x)); return y;
}
__device__ __forceinline__ float rcpf(float x) {
    float y; asm("rcp.approx.f32 %0, %1;" : "=f"(y) : "f"(x)); return y;
}
__device__ __forceinline__ float sigf(float x) {
    return rcpf(1.f + ex2f(-1.44269504f * x));
}
__device__ __forceinline__ float tanh_fast(float x) {
    return 2.f * rcpf(1.f + ex2f(-2.88539008f * x)) - 1.f;
}

// -------------------- init kernels -----------------------------------------
__global__ void zero_init_kernel() {
    size_t tid = (size_t)blockIdx.x * blockDim.x + threadIdx.x;
    size_t st  = (size_t)gridDim.x * blockDim.x;
    const size_t nh0 = (size_t)2 * 16 * 64 * 4096;
    const size_t nh1 = (size_t)2 * 16 * 6 * 4096;
    const size_t nc0 = (size_t)16 * 128 * 4096;
    const size_t nc1 = (size_t)16 * 12 * 4096;
    for (size_t i = tid; i < nh0; i += st) g_h0p[i] = 0u;
    for (size_t i = tid; i < nh1; i += st) g_h1p[i] = 0u;
    for (size_t i = tid; i < nc0; i += st) g_c0[i] = 0.f;
    for (size_t i = tid; i < nc1; i += st) g_c1[i] = 0.f;
}

__global__ void xprep_kernel(const float* __restrict__ hist) {
    int n = TSTEPS * 16 * 4096;
    for (int i = blockIdx.x * blockDim.x + threadIdx.x; i < n;
         i += gridDim.x * blockDim.x) {
        int px = i & 4095, b = (i >> 12) & 15, t = i >> 16;
        float v = hist[((size_t)b * TSTEPS + t) * 4096 + px];
        g_xp[((size_t)t * 16 + b) * 4096 + px] = pack_hf(v, 0.f);
    }
}

// Weights -> A-fragment order: [hb][chunk][ (tap*4+g)*128 + lane*4 + r ]
// reg r: m = lane/4 + (r&1)*8 ; pair = lane%4 + ((r>>1)&1)*4
__global__ void repack_w(const float* __restrict__ W, uint32_t* __restrict__ Wp,
                         int HID, int CIN, int NHB, int layer) {
    int total = NHB * NCHUNK * 4608;
    for (int idx = blockIdx.x * blockDim.x + threadIdx.x; idx < total;
         idx += gridDim.x * blockDim.x) {
        int wrd = idx % 4608, rest = idx / 4608;
        int c = rest % NCHUNK, hb = rest / NCHUNK;
        int r = wrd & 3, lane = (wrd >> 2) & 31, gt = wrd >> 7;
        int g = gt & 3, t = gt >> 2;
        int m  = (lane >> 2) + (r & 1) * 8;
        int pr = (lane & 3) + ((r >> 1) & 1) * 4;
        int p  = c * 8 + pr;
        int hid = hb * 16 + m;
        int k0 = -1, k1 = -1;
        if (layer == 0) {
            if (p < 64)       { k0 = 2 * p + 1; k1 = 2 * p + 2; }
            else if (p == 64) { k0 = 0; }
        } else {
            if (p < 64)      { k0 = 2 * p; k1 = 2 * p + 1; }
            else if (p < 70) { k0 = 128 + 2 * (p - 64); k1 = k0 + 1; }
        }
        float w0 = 0.f, w1 = 0.f;
        if (hid < HID) {
            if (k0 >= 0) w0 = W[((size_t)(g * HID + hid) * CIN + k0) * 9 + t];
            if (k1 >= 0) w1 = W[((size_t)(g * HID + hid) * CIN + k1) * 9 + t];
        }
        Wp[idx] = pack_hf(w0, w1);
    }
}

// -------------------- fused conv + LSTM step --------------------------------
// Grid (16 y-tiles, NHB, 16 batch), block 256 = 8 warps (wx 0..7).
// Warp: 16 hid x 4 gates x 32 px (8-px strip, 4 rows). 64 f32 accs/thread.
// Weights: per-tap LDG.128 fragments straight from global (L1-cached).
template <int NPA, int NPB, int HID>
__global__ __launch_bounds__(256, 2)
void conv_step(const uint32_t* __restrict__ actA,   // [b][NPA][4096]
               const uint32_t* __restrict__ actB,   // [b][NPB][4096]
               const uint32_t* __restrict__ Wg,     // [hb][9][4608] frag order
               const float*    __restrict__ bias,
               float*          __restrict__ cbuf,   // [b][HID][4096]
               uint32_t*       __restrict__ hout,   // [b][HID/2][4096]
               float*          __restrict__ hfout) {
    extern __shared__ uint32_t sm[];
    const int tid = threadIdx.x;
    const int lane = tid & 31, warp = tid >> 5;
    const int tg = lane & 3, gq = lane >> 2;
    const int wx = warp;                 // 0..7 (8-px strip)
    const int y0 = blockIdx.x * 4;
    const int hb = blockIdx.y;
    const int b  = blockIdx.z;
    const uint32_t* wgm = Wg + (size_t)hb * NCHUNK * 4608 + lane * 4;

    // zero halo columns (words 0..3 / 68..71) for all planes, both act buffers
    if (tid < 192) {
        int side = tid & 1, v = tid >> 1;          // v 0..95
        int r = v % 6, p = (v / 6) & 7, bfi = v / 48;
        uint32_t* dst = sm + bfi * SW_ACT + p * 440 + r * 72 + (side ? 68 : 0);
        *(uint4*)dst = make_uint4(0, 0, 0, 0);
    }

    float acc[4][4][4];
#pragma unroll
    for (int g = 0; g < 4; g++)
#pragma unroll
        for (int n = 0; n < 4; n++)
#pragma unroll
            for (int r = 0; r < 4; r++) acc[g][n][r] = 0.f;

    auto ldchunk = [&](int c, int bfi) {
#pragma unroll
        for (int k = 0; k < 3; k++) {
            int u = tid + k * 256;               // 768 uint4: act data
            int p = u & 7, rest = u >> 3;        // rest 0..95
            int r = rest % 6, seg = rest / 6;    // seg: 16 x 4px
            int pair = c * 8 + p;
            int y = y0 + r - 1;
            uint32_t* dst = sm + bfi * SW_ACT + p * 440 + r * 72 + 4 + seg * 4;
            const uint32_t* src = nullptr;
            if ((unsigned)y < 64u) {
                if (pair < NPA)
                    src = actA + ((size_t)b * NPA + pair) * 4096 + y * 64 + seg * 4;
                else if (pair < NPA + NPB)
                    src = actB + ((size_t)b * NPB + (pair - NPA)) * 4096 +
                          y * 64 + seg * 4;
            }
            if (src) cpa16(smaddr(dst), src);
            else     *(uint4*)dst = make_uint4(0, 0, 0, 0);
        }
        asm volatile("cp.async.commit_group;");
    };

    ldchunk(0, 0);

    for (int c = 0; c < NCHUNK; c++) {
        const int bfi = c & 1;
        if (c + 1 < NCHUNK) {
            ldchunk(c + 1, bfi ^ 1);
            asm volatile("cp.async.wait_group 1;");
        } else {
            asm volatile("cp.async.wait_group 0;");
        }
        __syncthreads();

        const uint32_t* aB = sm + bfi * SW_ACT;
        const uint32_t* wc = wgm + (size_t)c * 4608;

#pragma unroll
        for (int ky = 0; ky < 3; ky++) {
#pragma unroll
            for (int kx = 0; kx < 3; kx++) {
                const int t = ky * 3 + kx;
                const int cb = 4 + wx * 8 + gq + kx - 1;
                // stage weight fragments for this tap (4 x LDG.128, L1-hot)
                uint4 ah[4];
#pragma unroll
                for (int g = 0; g < 4; g++)
                    ah[g] = __ldg((const uint4*)(wc + (t * 4 + g) * 128));
                uint32_t bh[4][2];
#pragma unroll
                for (int nt = 0; nt < 4; nt++) {
                    int o0 = tg * 440 + (ky + nt) * 72 + cb;
                    bh[nt][0] = aB[o0]; bh[nt][1] = aB[o0 + 4 * 440];
                }
#pragma unroll
                for (int g = 0; g < 4; g++) {
#pragma unroll
                    for (int nt = 0; nt < 4; nt++)
                        mma_f16(acc[g][nt], (const uint32_t*)&ah[g],
                                bh[nt][0], bh[nt][1]);
                }
            }
        }
        __syncthreads();
    }

    // ---- LSTM epilogue -----------------------------------------------------
    const int xpx = wx * 8 + tg * 2;
#pragma unroll
    for (int part = 0; part < 2; part++) {
        const int hid = hb * 16 + gq + part * 8;
        const bool hv = (hid < HID);
        float bi = 0.f, bfv = 0.f, bo = 0.f, bg = 0.f;
        if (hv) {
            bi = bias[hid]; bfv = bias[HID + hid];
            bo = bias[2 * HID + hid]; bg = bias[3 * HID + hid];
        }
#pragma unroll
        for (int nt = 0; nt < 4; nt++) {
            const int y = y0 + nt;
            const size_t coff =
                ((size_t)(b * HID + (hv ? hid : 0))) * 4096 + (size_t)y * 64 + xpx;
            float2 c2 = hv ? *(const float2*)(cbuf + coff) : make_float2(0.f, 0.f);
            float cold[2] = {c2.x, c2.y}, hn[2];
#pragma unroll
            for (int q = 0; q < 2; q++) {
                float I = sigf(acc[0][nt][part * 2 + q] + bi);
                float F = sigf(acc[1][nt][part * 2 + q] + bfv);
                float O = sigf(acc[2][nt][part * 2 + q] + bo);
                float G = tanh_fast(acc[3][nt][part * 2 + q] + bg);
                float cn = F * cold[q] + I * G;
                cold[q] = cn;
                hn[q] = O * tanh_fast(cn);
            }
            if (hv) {
                *(float2*)(cbuf + coff) = make_float2(cold[0], cold[1]);
                if (hfout)
                    *(float2*)(hfout + coff) = make_float2(hn[0], hn[1]);
            }
            // pack channel pairs: partner hid^1 lives at lane^4
            float pn0 = __shfl_xor_sync(0xffffffffu, hn[0], 4);
            float pn1 = __shfl_xor_sync(0xffffffffu, hn[1], 4);
            if (((gq & 1) == 0) && hv) {
                const int qp = hid >> 1;
                const size_t ob =
                    ((size_t)b * (HID / 2) + qp) * 4096 + (size_t)y * 64 + xpx;
                *(uint2*)(hout + ob) =
                    make_uint2(pack_hf(hn[0], pn0), pack_hf(hn[1], pn1));
            }
        }
    }
}

// -------------------- host driver -------------------------------------------
extern "C" void kernel_launch(void* const* d_in, const int* in_sizes, int n_in,
                              void* d_out, int out_size) {
    (void)in_sizes; (void)n_in; (void)out_size;
    const float* history = (const float*)d_in[0];
    const float* W0 = (const float*)d_in[2];
    const float* b0 = (const float*)d_in[3];
    const float* W1 = (const float*)d_in[4];
    const float* b1 = (const float*)d_in[5];

    uint32_t *h0p, *h1p, *xp, *wp0, *wp1;
    float *c0, *c1, *h1f;
    cudaGetSymbolAddress((void**)&h0p, g_h0p);
    cudaGetSymbolAddress((void**)&h1p, g_h1p);
    cudaGetSymbolAddress((void**)&xp,  g_xp);
    cudaGetSymbolAddress((void**)&wp0, g_wp0);
    cudaGetSymbolAddress((void**)&wp1, g_wp1);
    cudaGetSymbolAddress((void**)&c0,  g_c0);
    cudaGetSymbolAddress((void**)&c1,  g_c1);
    cudaGetSymbolAddress((void**)&h1f, g_h1f);

    // lazily-created side stream + events (created on the first, uncaptured
    // correctness call; only their USE is captured into the graph)
    static cudaStream_t s2 = nullptr;
    static cudaEvent_t evP = nullptr, ev0[TSTEPS], ev1[TSTEPS];
    if (s2 == nullptr) {
        cudaStreamCreateWithFlags(&s2, cudaStreamNonBlocking);
        cudaEventCreateWithFlags(&evP, cudaEventDisableTiming);
        for (int t = 0; t < TSTEPS; t++) {
            cudaEventCreateWithFlags(&ev0[t], cudaEventDisableTiming);
            cudaEventCreateWithFlags(&ev1[t], cudaEventDisableTiming);
        }
    }

    zero_init_kernel<<<1024, 256>>>();
    xprep_kernel<<<768, 256>>>(history);
    repack_w<<<324, 256>>>(W0, wp0, 128, 129, 8, 0);
    repack_w<<<41, 256>>>(W1, wp1, 12, 140, 1, 1);
    cudaEventRecord(evP, 0);
    cudaStreamWaitEvent(s2, evP, 0);

    const size_t H0SZ = (size_t)16 * 64 * 4096;
    const size_t H1SZ = (size_t)16 * 6 * 4096;

    int pa = 0;
    for (int t = 0; t < TSTEPS; t++) {
        const uint32_t* h0r = h0p + (size_t)pa * H0SZ;
        uint32_t*       h0w = h0p + (size_t)(1 - pa) * H0SZ;
        const uint32_t* h1r = h1p + (size_t)pa * H1SZ;
        uint32_t*       h1w = h1p + (size_t)(1 - pa) * H1SZ;

        // L0(t) overwrites h0 buffer 'pa' ... which L1(t-2) read: guard.
        if (t >= 2) cudaStreamWaitEvent(0, ev1[t - 2], 0);

        conv_step<64, 1, 128><<<dim3(16, 8, 16), 256, SMEM_BYTES>>>(
            h0r, xp + (size_t)t * 16 * 4096, wp0, b0, c0, h0w, nullptr);
        cudaEventRecord(ev0[t], 0);

        // L1(t) on side stream: depends only on L0(t) + L1(t-1); overlaps L0(t+1)
        cudaStreamWaitEvent(s2, ev0[t], 0);
        conv_step<64, 6, 12><<<dim3(16, 1, 16), 256, SMEM_BYTES, s2>>>(
            h0w, h1r, wp1, b1, c1, h1w, (t == TSTEPS - 1) ? h1f : nullptr);
        cudaEventRecord(ev1[t], s2);

        pa ^= 1;
    }

    cudaStreamWaitEvent(0, ev1[TSTEPS - 1], 0);
    cudaMemcpyAsync(d_out, h1f, (size_t)16 * 12 * 4096 * sizeof(float),
                    cudaMemcpyDeviceToDevice);
}

// round 14
// speedup vs baseline: 6.4881x; 1.1029x over previous
#include <cuda_runtime.h>
#include <cuda_fp16.h>
#include <math.h>
#include <stdint.h>

// ---------------------------------------------------------------------------
// ConvLSTM (2 layers, 12 steps) — tensor-core implicit GEMM, pure fp16.
// R14: L0's x channel (INPUT_DIM=1) moved out of the MMA K dimension onto the
//      idle fma pipe (scalar fp32 taps in the epilogue). L0 K = exactly 64
//      h-pairs -> NCHUNK 9 -> 8, MMA count -11% with zero K padding waste.
//      conv_step core otherwise identical to R11/R13 (256 thr, 2 blocks/SM).
//      L1 on side stream (R13) kept.
// Weights LDG.128'd straight from frag-ordered global (L1-hot, no smem stage).
// Activations stored as channel-pair planes: uint32 = {fp16 ch2p | fp16 ch2p+1}.
// ---------------------------------------------------------------------------

#define TSTEPS 12

__device__ uint32_t g_h0p[2u * 16u * 64u * 4096u];   // h0 pair planes (fp16x2)
__device__ uint32_t g_h1p[2u * 16u * 6u  * 4096u];   // h1 pair planes
__device__ float    g_xf [12u * 16u * 4096u];        // x float planes per t
__device__ float    g_c0 [16u * 128u * 4096u];
__device__ float    g_c1 [16u * 12u  * 4096u];
__device__ float    g_h1f[16u * 12u * 4096u];        // float h1 (output, t=11)
__device__ uint32_t g_wp0[8u * 8u * 4608u];          // frag-packed fp16 weights
__device__ uint32_t g_wp1[1u * 9u * 4608u];
__device__ float    g_wx [128u * 36u];               // x-channel weights [hid][g][tap]

#define SW_ACT   3520u              // one act chunk: 8 planes * 440 words
#define SW_XS    (2u * SW_ACT)      // x tile: 6 rows * 66 floats (+pad)
#define SMEM_BYTES ((2u * SW_ACT + 400u) * 4u)       // 29,760 B

// -------------------- helpers ----------------------------------------------
__device__ __forceinline__ void mma_f16(float* d, const uint32_t* a,
                                        uint32_t b0, uint32_t b1) {
    asm volatile(
        "mma.sync.aligned.m16n8k16.row.col.f32.f16.f16.f32 "
        "{%0,%1,%2,%3}, {%4,%5,%6,%7}, {%8,%9}, {%0,%1,%2,%3};"
        : "+f"(d[0]), "+f"(d[1]), "+f"(d[2]), "+f"(d[3])
        : "r"(a[0]), "r"(a[1]), "r"(a[2]), "r"(a[3]), "r"(b0), "r"(b1));
}
__device__ __forceinline__ uint32_t smaddr(const void* p) {
    return (uint32_t)__cvta_generic_to_shared(p);
}
__device__ __forceinline__ void cpa16(uint32_t dst, const void* src) {
    asm volatile("cp.async.cg.shared.global [%0], [%1], 16;" :: "r"(dst), "l"(src));
}
__device__ __forceinline__ uint32_t pack_hf(float a, float b) {
    __half2 h = __floats2half2_rn(a, b);
    return *(uint32_t*)&h;
}
__device__ __forceinline__ float ex2f(float x) {
    float y; asm("ex2.approx.f32 %0, %1;" : "=f"(y) : "f"(x)); return y;
}
__device__ __forceinline__ float rcpf(float x) {
    float y; asm("rcp.approx.f32 %0, %1;" : "=f"(y) : "f"(x)); return y;
}
__device__ __forceinline__ float sigf(float x) {
    return rcpf(1.f + ex2f(-1.44269504f * x));
}
__device__ __forceinline__ float tanh_fast(float x) {
    return 2.f * rcpf(1.f + ex2f(-2.88539008f * x)) - 1.f;
}

// -------------------- init kernels -----------------------------------------
__global__ void zero_init_kernel() {
    size_t tid = (size_t)blockIdx.x * blockDim.x + threadIdx.x;
    size_t st  = (size_t)gridDim.x * blockDim.x;
    const size_t nh0 = (size_t)2 * 16 * 64 * 4096;
    const size_t nh1 = (size_t)2 * 16 * 6 * 4096;
    const size_t nc0 = (size_t)16 * 128 * 4096;
    const size_t nc1 = (size_t)16 * 12 * 4096;
    for (size_t i = tid; i < nh0; i += st) g_h0p[i] = 0u;
    for (size_t i = tid; i < nh1; i += st) g_h1p[i] = 0u;
    for (size_t i = tid; i < nc0; i += st) g_c0[i] = 0.f;
    for (size_t i = tid; i < nc1; i += st) g_c1[i] = 0.f;
}

__global__ void xprep_kernel(const float* __restrict__ hist) {
    int n = TSTEPS * 16 * 4096;
    for (int i = blockIdx.x * blockDim.x + threadIdx.x; i < n;
         i += gridDim.x * blockDim.x) {
        int px = i & 4095, b = (i >> 12) & 15, t = i >> 16;
        g_xf[((size_t)t * 16 + b) * 4096 + px] =
            hist[((size_t)b * TSTEPS + t) * 4096 + px];
    }
}

// x-channel weights: WX[hid][gate][tap] = W0[(g*128+hid), cin=0, tap]
__global__ void repack_wx(const float* __restrict__ W, float* __restrict__ WX) {
    int idx = blockIdx.x * blockDim.x + threadIdx.x;
    if (idx < 128 * 36) {
        int hid = idx / 36, rem = idx % 36;
        int g = rem / 9, t = rem % 9;
        WX[idx] = W[((size_t)(g * 128 + hid) * 129 + 0) * 9 + t];
    }
}

// Weights -> A-fragment order: [hb][chunk][ (tap*4+g)*128 + lane*4 + r ]
// reg r: m = lane/4 + (r&1)*8 ; pair = lane%4 + ((r>>1)&1)*4
__global__ void repack_w(const float* __restrict__ W, uint32_t* __restrict__ Wp,
                         int HID, int CIN, int NHB, int NCH, int layer) {
    int total = NHB * NCH * 4608;
    for (int idx = blockIdx.x * blockDim.x + threadIdx.x; idx < total;
         idx += gridDim.x * blockDim.x) {
        int wrd = idx % 4608, rest = idx / 4608;
        int c = rest % NCH, hb = rest / NCH;
        int r = wrd & 3, lane = (wrd >> 2) & 31, gt = wrd >> 7;
        int g = gt & 3, t = gt >> 2;
        int m  = (lane >> 2) + (r & 1) * 8;
        int pr = (lane & 3) + ((r >> 1) & 1) * 4;
        int p  = c * 8 + pr;
        int hid = hb * 16 + m;
        int k0 = -1, k1 = -1;
        if (layer == 0) {
            // p in [0,63]: h0 pairs only (channels 1..128); x handled scalar
            k0 = 2 * p + 1; k1 = 2 * p + 2;
        } else {
            if (p < 64)      { k0 = 2 * p; k1 = 2 * p + 1; }
            else if (p < 70) { k0 = 128 + 2 * (p - 64); k1 = k0 + 1; }
        }
        float w0 = 0.f, w1 = 0.f;
        if (hid < HID) {
            if (k0 >= 0 && k0 < CIN) w0 = W[((size_t)(g * HID + hid) * CIN + k0) * 9 + t];
            if (k1 >= 0 && k1 < CIN) w1 = W[((size_t)(g * HID + hid) * CIN + k1) * 9 + t];
        }
        Wp[idx] = pack_hf(w0, w1);
    }
}

// -------------------- fused conv + LSTM step --------------------------------
// Grid (16 y-tiles, NHB, 16 batch), block 256 = 8 warps (wx 0..7).
// Warp: 16 hid x 4 gates x 32 px (8-px strip, 4 rows). 64 f32 accs/thread.
// Weights: per-tap LDG.128 fragments straight from global (L1-cached).
// XS: scalar fp32 x-channel taps added in the epilogue (fma pipe).
template <int NPA, int NPB, int NCH, int XS, int HID>
__global__ __launch_bounds__(256, 2)
void conv_step(const uint32_t* __restrict__ actA,   // [b][NPA][4096]
               const uint32_t* __restrict__ actB,   // [b][NPB][4096]
               const uint32_t* __restrict__ Wg,     // [hb][NCH][4608] frag order
               const float*    __restrict__ bias,
               const float*    __restrict__ xplane, // [b][4096] (XS only)
               const float*    __restrict__ wxt,    // [hid][4][9]  (XS only)
               float*          __restrict__ cbuf,   // [b][HID][4096]
               uint32_t*       __restrict__ hout,   // [b][HID/2][4096]
               float*          __restrict__ hfout) {
    extern __shared__ uint32_t sm[];
    float* xs = (float*)(sm + SW_XS);    // [6][66]
    const int tid = threadIdx.x;
    const int lane = tid & 31, warp = tid >> 5;
    const int tg = lane & 3, gq = lane >> 2;
    const int wx = warp;                 // 0..7 (8-px strip)
    const int y0 = blockIdx.x * 4;
    const int hb = blockIdx.y;
    const int b  = blockIdx.z;
    const uint32_t* wgm = Wg + (size_t)hb * NCH * 4608 + lane * 4;

    // zero halo columns (words 0..3 / 68..71) for all planes, both act buffers
    if (tid < 192) {
        int side = tid & 1, v = tid >> 1;          // v 0..95
        int r = v % 6, p = (v / 6) & 7, bfi = v / 48;
        uint32_t* dst = sm + bfi * SW_ACT + p * 440 + r * 72 + (side ? 68 : 0);
        *(uint4*)dst = make_uint4(0, 0, 0, 0);
    }

    // x tile (with halo): xs[r][cc] = x[y0+r-1][cc-1], zero-padded
    if (XS) {
        const float* xb = xplane + (size_t)b * 4096;
        for (int u = tid; u < 396; u += 256) {
            int r = u / 66, cc = u - r * 66;
            int gy = y0 + r - 1, gx = cc - 1;
            float v = 0.f;
            if ((unsigned)gy < 64u && (unsigned)gx < 64u) v = xb[gy * 64 + gx];
            xs[u] = v;
        }
    }

    float acc[4][4][4];
#pragma unroll
    for (int g = 0; g < 4; g++)
#pragma unroll
        for (int n = 0; n < 4; n++)
#pragma unroll
            for (int r = 0; r < 4; r++) acc[g][n][r] = 0.f;

    auto ldchunk = [&](int c, int bfi) {
#pragma unroll
        for (int k = 0; k < 3; k++) {
            int u = tid + k * 256;               // 768 uint4: act data
            int p = u & 7, rest = u >> 3;        // rest 0..95
            int r = rest % 6, seg = rest / 6;    // seg: 16 x 4px
            int pair = c * 8 + p;
            int y = y0 + r - 1;
            uint32_t* dst = sm + bfi * SW_ACT + p * 440 + r * 72 + 4 + seg * 4;
            const uint32_t* src = nullptr;
            if ((unsigned)y < 64u) {
                if (pair < NPA)
                    src = actA + ((size_t)b * NPA + pair) * 4096 + y * 64 + seg * 4;
                else if (pair < NPA + NPB)
                    src = actB + ((size_t)b * NPB + (pair - NPA)) * 4096 +
                          y * 64 + seg * 4;
            }
            if (src) cpa16(smaddr(dst), src);
            else     *(uint4*)dst = make_uint4(0, 0, 0, 0);
        }
        asm volatile("cp.async.commit_group;");
    };

    ldchunk(0, 0);

    for (int c = 0; c < NCH; c++) {
        const int bfi = c & 1;
        if (c + 1 < NCH) {
            ldchunk(c + 1, bfi ^ 1);
            asm volatile("cp.async.wait_group 1;");
        } else {
            asm volatile("cp.async.wait_group 0;");
        }
        __syncthreads();

        const uint32_t* aB = sm + bfi * SW_ACT;
        const uint32_t* wc = wgm + (size_t)c * 4608;

#pragma unroll
        for (int ky = 0; ky < 3; ky++) {
#pragma unroll
            for (int kx = 0; kx < 3; kx++) {
                const int t = ky * 3 + kx;
                const int cb = 4 + wx * 8 + gq + kx - 1;
                // stage weight fragments for this tap (4 x LDG.128, L1-hot)
                uint4 ah[4];
#pragma unroll
                for (int g = 0; g < 4; g++)
                    ah[g] = __ldg((const uint4*)(wc + (t * 4 + g) * 128));
                uint32_t bh[4][2];
#pragma unroll
                for (int nt = 0; nt < 4; nt++) {
                    int o0 = tg * 440 + (ky + nt) * 72 + cb;
                    bh[nt][0] = aB[o0]; bh[nt][1] = aB[o0 + 4 * 440];
                }
#pragma unroll
                for (int g = 0; g < 4; g++) {
#pragma unroll
                    for (int nt = 0; nt < 4; nt++)
                        mma_f16(acc[g][nt], (const uint32_t*)&ah[g],
                                bh[nt][0], bh[nt][1]);
                }
            }
        }
        __syncthreads();
    }

    const int xpx = wx * 8 + tg * 2;

    // ---- x-channel scalar taps (fp32, fma pipe) ----------------------------
    if (XS) {
        float xv[6][4];
#pragma unroll
        for (int r = 0; r < 6; r++)
#pragma unroll
            for (int j = 0; j < 4; j++) xv[r][j] = xs[r * 66 + xpx + j];
#pragma unroll
        for (int part = 0; part < 2; part++) {
            const int hid = hb * 16 + gq + part * 8;
            const float* wrow = wxt + (size_t)hid * 36;
#pragma unroll
            for (int g = 0; g < 4; g++) {
                float wv[9];
#pragma unroll
                for (int t9 = 0; t9 < 9; t9++) wv[t9] = __ldg(wrow + g * 9 + t9);
#pragma unroll
                for (int nt = 0; nt < 4; nt++) {
#pragma unroll
                    for (int q = 0; q < 2; q++) {
                        float s = acc[g][nt][part * 2 + q];
#pragma unroll
                        for (int ky = 0; ky < 3; ky++)
#pragma unroll
                            for (int kx = 0; kx < 3; kx++)
                                s = fmaf(wv[ky * 3 + kx], xv[nt + ky][q + kx], s);
                        acc[g][nt][part * 2 + q] = s;
                    }
                }
            }
        }
    }

    // ---- LSTM epilogue -----------------------------------------------------
#pragma unroll
    for (int part = 0; part < 2; part++) {
        const int hid = hb * 16 + gq + part * 8;
        const bool hv = (hid < HID);
        float bi = 0.f, bfv = 0.f, bo = 0.f, bg = 0.f;
        if (hv) {
            bi = bias[hid]; bfv = bias[HID + hid];
            bo = bias[2 * HID + hid]; bg = bias[3 * HID + hid];
        }
#pragma unroll
        for (int nt = 0; nt < 4; nt++) {
            const int y = y0 + nt;
            const size_t coff =
                ((size_t)(b * HID + (hv ? hid : 0))) * 4096 + (size_t)y * 64 + xpx;
            float2 c2 = hv ? *(const float2*)(cbuf + coff) : make_float2(0.f, 0.f);
            float cold[2] = {c2.x, c2.y}, hn[2];
#pragma unroll
            for (int q = 0; q < 2; q++) {
                float I = sigf(acc[0][nt][part * 2 + q] + bi);
                float F = sigf(acc[1][nt][part * 2 + q] + bfv);
                float O = sigf(acc[2][nt][part * 2 + q] + bo);
                float G = tanh_fast(acc[3][nt][part * 2 + q] + bg);
                float cn = F * cold[q] + I * G;
                cold[q] = cn;
                hn[q] = O * tanh_fast(cn);
            }
            if (hv) {
                *(float2*)(cbuf + coff) = make_float2(cold[0], cold[1]);
                if (hfout)
                    *(float2*)(hfout + coff) = make_float2(hn[0], hn[1]);
            }
            // pack channel pairs: partner hid^1 lives at lane^4
            float pn0 = __shfl_xor_sync(0xffffffffu, hn[0], 4);
            float pn1 = __shfl_xor_sync(0xffffffffu, hn[1], 4);
            if (((gq & 1) == 0) && hv) {
                const int qp = hid >> 1;
                const size_t ob =
                    ((size_t)b * (HID / 2) + qp) * 4096 + (size_t)y * 64 + xpx;
                *(uint2*)(hout + ob) =
                    make_uint2(pack_hf(hn[0], pn0), pack_hf(hn[1], pn1));
            }
        }
    }
}

// -------------------- host driver -------------------------------------------
extern "C" void kernel_launch(void* const* d_in, const int* in_sizes, int n_in,
                              void* d_out, int out_size) {
    (void)in_sizes; (void)n_in; (void)out_size;
    const float* history = (const float*)d_in[0];
    const float* W0 = (const float*)d_in[2];
    const float* b0 = (const float*)d_in[3];
    const float* W1 = (const float*)d_in[4];
    const float* b1 = (const float*)d_in[5];

    uint32_t *h0p, *h1p, *wp0, *wp1;
    float *xf, *c0, *c1, *h1f, *wxt;
    cudaGetSymbolAddress((void**)&h0p, g_h0p);
    cudaGetSymbolAddress((void**)&h1p, g_h1p);
    cudaGetSymbolAddress((void**)&xf,  g_xf);
    cudaGetSymbolAddress((void**)&wp0, g_wp0);
    cudaGetSymbolAddress((void**)&wp1, g_wp1);
    cudaGetSymbolAddress((void**)&c0,  g_c0);
    cudaGetSymbolAddress((void**)&c1,  g_c1);
    cudaGetSymbolAddress((void**)&h1f, g_h1f);
    cudaGetSymbolAddress((void**)&wxt, g_wx);

    // lazily-created side stream + events (created on the first, uncaptured
    // correctness call; only their USE is captured into the graph)
    static cudaStream_t s2 = nullptr;
    static cudaEvent_t evP = nullptr, ev0[TSTEPS], ev1[TSTEPS];
    if (s2 == nullptr) {
        cudaStreamCreateWithFlags(&s2, cudaStreamNonBlocking);
        cudaEventCreateWithFlags(&evP, cudaEventDisableTiming);
        for (int t = 0; t < TSTEPS; t++) {
            cudaEventCreateWithFlags(&ev0[t], cudaEventDisableTiming);
            cudaEventCreateWithFlags(&ev1[t], cudaEventDisableTiming);
        }
    }

    zero_init_kernel<<<1024, 256>>>();
    xprep_kernel<<<768, 256>>>(history);
    repack_w<<<288, 256>>>(W0, wp0, 128, 129, 8, 8, 0);
    repack_w<<<41, 256>>>(W1, wp1, 12, 140, 1, 9, 1);
    repack_wx<<<18, 256>>>(W0, wxt);
    cudaEventRecord(evP, 0);
    cudaStreamWaitEvent(s2, evP, 0);

    const size_t H0SZ = (size_t)16 * 64 * 4096;
    const size_t H1SZ = (size_t)16 * 6 * 4096;

    int pa = 0;
    for (int t = 0; t < TSTEPS; t++) {
        const uint32_t* h0r = h0p + (size_t)pa * H0SZ;
        uint32_t*       h0w = h0p + (size_t)(1 - pa) * H0SZ;
        const uint32_t* h1r = h1p + (size_t)pa * H1SZ;
        uint32_t*       h1w = h1p + (size_t)(1 - pa) * H1SZ;

        // L0(t) overwrites h0 buffer 'pa' ... which L1(t-2) read: guard.
        if (t >= 2) cudaStreamWaitEvent(0, ev1[t - 2], 0);

        conv_step<64, 0, 8, 1, 128><<<dim3(16, 8, 16), 256, SMEM_BYTES>>>(
            h0r, nullptr, wp0, b0, xf + (size_t)t * 16 * 4096, wxt,
            c0, h0w, nullptr);
        cudaEventRecord(ev0[t], 0);

        // L1(t) on side stream: depends only on L0(t) + L1(t-1); overlaps L0(t+1)
        cudaStreamWaitEvent(s2, ev0[t], 0);
        conv_step<64, 6, 9, 0, 12><<<dim3(16, 1, 16), 256, SMEM_BYTES, s2>>>(
            h0w, h1r, wp1, b1, nullptr, nullptr,
            c1, h1w, (t == TSTEPS - 1) ? h1f : nullptr);
        cudaEventRecord(ev1[t], s2);

        pa ^= 1;
    }

    cudaStreamWaitEvent(0, ev1[TSTEPS - 1], 0);
    cudaMemcpyAsync(d_out, h1f, (size_t)16 * 12 * 4096 * sizeof(float),
                    cudaMemcpyDeviceToDevice);
}

// round 15
// speedup vs baseline: 6.4899x; 1.0003x over previous
#include <cuda_runtime.h>
#include <cuda_fp16.h>
#include <math.h>
#include <stdint.h>

// ---------------------------------------------------------------------------
// ConvLSTM (2 layers, 12 steps) — tensor-core implicit GEMM, pure fp16.
// R14: L0's x channel (INPUT_DIM=1) moved out of the MMA K dimension onto the
//      idle fma pipe (scalar fp32 taps in the epilogue). L0 K = exactly 64
//      h-pairs -> NCHUNK 9 -> 8, MMA count -11% with zero K padding waste.
//      conv_step core otherwise identical to R11/R13 (256 thr, 2 blocks/SM).
//      L1 on side stream (R13) kept.
// Weights LDG.128'd straight from frag-ordered global (L1-hot, no smem stage).
// Activations stored as channel-pair planes: uint32 = {fp16 ch2p | fp16 ch2p+1}.
// ---------------------------------------------------------------------------

#define TSTEPS 12

__device__ uint32_t g_h0p[2u * 16u * 64u * 4096u];   // h0 pair planes (fp16x2)
__device__ uint32_t g_h1p[2u * 16u * 6u  * 4096u];   // h1 pair planes
__device__ float    g_xf [12u * 16u * 4096u];        // x float planes per t
__device__ float    g_c0 [16u * 128u * 4096u];
__device__ float    g_c1 [16u * 12u  * 4096u];
__device__ float    g_h1f[16u * 12u * 4096u];        // float h1 (output, t=11)
__device__ uint32_t g_wp0[8u * 8u * 4608u];          // frag-packed fp16 weights
__device__ uint32_t g_wp1[1u * 9u * 4608u];
__device__ float    g_wx [128u * 36u];               // x-channel weights [hid][g][tap]

#define SW_ACT   3520u              // one act chunk: 8 planes * 440 words
#define SW_XS    (2u * SW_ACT)      // x tile: 6 rows * 66 floats (+pad)
#define SMEM_BYTES ((2u * SW_ACT + 400u) * 4u)       // 29,760 B

// -------------------- helpers ----------------------------------------------
__device__ __forceinline__ void mma_f16(float* d, const uint32_t* a,
                                        uint32_t b0, uint32_t b1) {
    asm volatile(
        "mma.sync.aligned.m16n8k16.row.col.f32.f16.f16.f32 "
        "{%0,%1,%2,%3}, {%4,%5,%6,%7}, {%8,%9}, {%0,%1,%2,%3};"
        : "+f"(d[0]), "+f"(d[1]), "+f"(d[2]), "+f"(d[3])
        : "r"(a[0]), "r"(a[1]), "r"(a[2]), "r"(a[3]), "r"(b0), "r"(b1));
}
__device__ __forceinline__ uint32_t smaddr(const void* p) {
    return (uint32_t)__cvta_generic_to_shared(p);
}
__device__ __forceinline__ void cpa16(uint32_t dst, const void* src) {
    asm volatile("cp.async.cg.shared.global [%0], [%1], 16;" :: "r"(dst), "l"(src));
}
__device__ __forceinline__ uint32_t pack_hf(float a, float b) {
    __half2 h = __floats2half2_rn(a, b);
    return *(uint32_t*)&h;
}
__device__ __forceinline__ float ex2f(float x) {
    float y; asm("ex2.approx.f32 %0, %1;" : "=f"(y) : "f"(x)); return y;
}
__device__ __forceinline__ float rcpf(float x) {
    float y; asm("rcp.approx.f32 %0, %1;" : "=f"(y) : "f"(x)); return y;
}
__device__ __forceinline__ float sigf(float x) {
    return rcpf(1.f + ex2f(-1.44269504f * x));
}
__device__ __forceinline__ float tanh_fast(float x) {
    return 2.f * rcpf(1.f + ex2f(-2.88539008f * x)) - 1.f;
}

// -------------------- init kernels -----------------------------------------
__global__ void zero_init_kernel() {
    size_t tid = (size_t)blockIdx.x * blockDim.x + threadIdx.x;
    size_t st  = (size_t)gridDim.x * blockDim.x;
    const size_t nh0 = (size_t)2 * 16 * 64 * 4096;
    const size_t nh1 = (size_t)2 * 16 * 6 * 4096;
    const size_t nc0 = (size_t)16 * 128 * 4096;
    const size_t nc1 = (size_t)16 * 12 * 4096;
    for (size_t i = tid; i < nh0; i += st) g_h0p[i] = 0u;
    for (size_t i = tid; i < nh1; i += st) g_h1p[i] = 0u;
    for (size_t i = tid; i < nc0; i += st) g_c0[i] = 0.f;
    for (size_t i = tid; i < nc1; i += st) g_c1[i] = 0.f;
}

__global__ void xprep_kernel(const float* __restrict__ hist) {
    int n = TSTEPS * 16 * 4096;
    for (int i = blockIdx.x * blockDim.x + threadIdx.x; i < n;
         i += gridDim.x * blockDim.x) {
        int px = i & 4095, b = (i >> 12) & 15, t = i >> 16;
        g_xf[((size_t)t * 16 + b) * 4096 + px] =
            hist[((size_t)b * TSTEPS + t) * 4096 + px];
    }
}

// x-channel weights: WX[hid][gate][tap] = W0[(g*128+hid), cin=0, tap]
__global__ void repack_wx(const float* __restrict__ W, float* __restrict__ WX) {
    int idx = blockIdx.x * blockDim.x + threadIdx.x;
    if (idx < 128 * 36) {
        int hid = idx / 36, rem = idx % 36;
        int g = rem / 9, t = rem % 9;
        WX[idx] = W[((size_t)(g * 128 + hid) * 129 + 0) * 9 + t];
    }
}

// Weights -> A-fragment order: [hb][chunk][ (tap*4+g)*128 + lane*4 + r ]
// reg r: m = lane/4 + (r&1)*8 ; pair = lane%4 + ((r>>1)&1)*4
__global__ void repack_w(const float* __restrict__ W, uint32_t* __restrict__ Wp,
                         int HID, int CIN, int NHB, int NCH, int layer) {
    int total = NHB * NCH * 4608;
    for (int idx = blockIdx.x * blockDim.x + threadIdx.x; idx < total;
         idx += gridDim.x * blockDim.x) {
        int wrd = idx % 4608, rest = idx / 4608;
        int c = rest % NCH, hb = rest / NCH;
        int r = wrd & 3, lane = (wrd >> 2) & 31, gt = wrd >> 7;
        int g = gt & 3, t = gt >> 2;
        int m  = (lane >> 2) + (r & 1) * 8;
        int pr = (lane & 3) + ((r >> 1) & 1) * 4;
        int p  = c * 8 + pr;
        int hid = hb * 16 + m;
        int k0 = -1, k1 = -1;
        if (layer == 0) {
            // p in [0,63]: h0 pairs only (channels 1..128); x handled scalar
            k0 = 2 * p + 1; k1 = 2 * p + 2;
        } else {
            if (p < 64)      { k0 = 2 * p; k1 = 2 * p + 1; }
            else if (p < 70) { k0 = 128 + 2 * (p - 64); k1 = k0 + 1; }
        }
        float w0 = 0.f, w1 = 0.f;
        if (hid < HID) {
            if (k0 >= 0 && k0 < CIN) w0 = W[((size_t)(g * HID + hid) * CIN + k0) * 9 + t];
            if (k1 >= 0 && k1 < CIN) w1 = W[((size_t)(g * HID + hid) * CIN + k1) * 9 + t];
        }
        Wp[idx] = pack_hf(w0, w1);
    }
}

// -------------------- fused conv + LSTM step --------------------------------
// Grid (16 y-tiles, NHB, 16 batch), block 256 = 8 warps (wx 0..7).
// Warp: 16 hid x 4 gates x 32 px (8-px strip, 4 rows). 64 f32 accs/thread.
// Weights: per-tap LDG.128 fragments straight from global (L1-cached).
// XS: scalar fp32 x-channel taps added in the epilogue (fma pipe).
template <int NPA, int NPB, int NCH, int XS, int HID>
__global__ __launch_bounds__(256, 2)
void conv_step(const uint32_t* __restrict__ actA,   // [b][NPA][4096]
               const uint32_t* __restrict__ actB,   // [b][NPB][4096]
               const uint32_t* __restrict__ Wg,     // [hb][NCH][4608] frag order
               const float*    __restrict__ bias,
               const float*    __restrict__ xplane, // [b][4096] (XS only)
               const float*    __restrict__ wxt,    // [hid][4][9]  (XS only)
               float*          __restrict__ cbuf,   // [b][HID][4096]
               uint32_t*       __restrict__ hout,   // [b][HID/2][4096]
               float*          __restrict__ hfout) {
    extern __shared__ uint32_t sm[];
    float* xs = (float*)(sm + SW_XS);    // [6][66]
    const int tid = threadIdx.x;
    const int lane = tid & 31, warp = tid >> 5;
    const int tg = lane & 3, gq = lane >> 2;
    const int wx = warp;                 // 0..7 (8-px strip)
    const int y0 = blockIdx.x * 4;
    const int hb = blockIdx.y;
    const int b  = blockIdx.z;
    const uint32_t* wgm = Wg + (size_t)hb * NCH * 4608 + lane * 4;

    // zero halo columns (words 0..3 / 68..71) for all planes, both act buffers
    if (tid < 192) {
        int side = tid & 1, v = tid >> 1;          // v 0..95
        int r = v % 6, p = (v / 6) & 7, bfi = v / 48;
        uint32_t* dst = sm + bfi * SW_ACT + p * 440 + r * 72 + (side ? 68 : 0);
        *(uint4*)dst = make_uint4(0, 0, 0, 0);
    }

    // x tile (with halo): xs[r][cc] = x[y0+r-1][cc-1], zero-padded
    if (XS) {
        const float* xb = xplane + (size_t)b * 4096;
        for (int u = tid; u < 396; u += 256) {
            int r = u / 66, cc = u - r * 66;
            int gy = y0 + r - 1, gx = cc - 1;
            float v = 0.f;
            if ((unsigned)gy < 64u && (unsigned)gx < 64u) v = xb[gy * 64 + gx];
            xs[u] = v;
        }
    }

    float acc[4][4][4];
#pragma unroll
    for (int g = 0; g < 4; g++)
#pragma unroll
        for (int n = 0; n < 4; n++)
#pragma unroll
            for (int r = 0; r < 4; r++) acc[g][n][r] = 0.f;

    auto ldchunk = [&](int c, int bfi) {
#pragma unroll
        for (int k = 0; k < 3; k++) {
            int u = tid + k * 256;               // 768 uint4: act data
            int p = u & 7, rest = u >> 3;        // rest 0..95
            int r = rest % 6, seg = rest / 6;    // seg: 16 x 4px
            int pair = c * 8 + p;
            int y = y0 + r - 1;
            uint32_t* dst = sm + bfi * SW_ACT + p * 440 + r * 72 + 4 + seg * 4;
            const uint32_t* src = nullptr;
            if ((unsigned)y < 64u) {
                if (pair < NPA)
                    src = actA + ((size_t)b * NPA + pair) * 4096 + y * 64 + seg * 4;
                else if (pair < NPA + NPB)
                    src = actB + ((size_t)b * NPB + (pair - NPA)) * 4096 +
                          y * 64 + seg * 4;
            }
            if (src) cpa16(smaddr(dst), src);
            else     *(uint4*)dst = make_uint4(0, 0, 0, 0);
        }
        asm volatile("cp.async.commit_group;");
    };

    ldchunk(0, 0);

    for (int c = 0; c < NCH; c++) {
        const int bfi = c & 1;
        if (c + 1 < NCH) {
            ldchunk(c + 1, bfi ^ 1);
            asm volatile("cp.async.wait_group 1;");
        } else {
            asm volatile("cp.async.wait_group 0;");
        }
        __syncthreads();

        const uint32_t* aB = sm + bfi * SW_ACT;
        const uint32_t* wc = wgm + (size_t)c * 4608;

#pragma unroll
        for (int ky = 0; ky < 3; ky++) {
#pragma unroll
            for (int kx = 0; kx < 3; kx++) {
                const int t = ky * 3 + kx;
                const int cb = 4 + wx * 8 + gq + kx - 1;
                // stage weight fragments for this tap (4 x LDG.128, L1-hot)
                uint4 ah[4];
#pragma unroll
                for (int g = 0; g < 4; g++)
                    ah[g] = __ldg((const uint4*)(wc + (t * 4 + g) * 128));
                uint32_t bh[4][2];
#pragma unroll
                for (int nt = 0; nt < 4; nt++) {
                    int o0 = tg * 440 + (ky + nt) * 72 + cb;
                    bh[nt][0] = aB[o0]; bh[nt][1] = aB[o0 + 4 * 440];
                }
#pragma unroll
                for (int g = 0; g < 4; g++) {
#pragma unroll
                    for (int nt = 0; nt < 4; nt++)
                        mma_f16(acc[g][nt], (const uint32_t*)&ah[g],
                                bh[nt][0], bh[nt][1]);
                }
            }
        }
        __syncthreads();
    }

    const int xpx = wx * 8 + tg * 2;

    // ---- x-channel scalar taps (fp32, fma pipe) ----------------------------
    if (XS) {
        float xv[6][4];
#pragma unroll
        for (int r = 0; r < 6; r++)
#pragma unroll
            for (int j = 0; j < 4; j++) xv[r][j] = xs[r * 66 + xpx + j];
#pragma unroll
        for (int part = 0; part < 2; part++) {
            const int hid = hb * 16 + gq + part * 8;
            const float* wrow = wxt + (size_t)hid * 36;
#pragma unroll
            for (int g = 0; g < 4; g++) {
                float wv[9];
#pragma unroll
                for (int t9 = 0; t9 < 9; t9++) wv[t9] = __ldg(wrow + g * 9 + t9);
#pragma unroll
                for (int nt = 0; nt < 4; nt++) {
#pragma unroll
                    for (int q = 0; q < 2; q++) {
                        float s = acc[g][nt][part * 2 + q];
#pragma unroll
                        for (int ky = 0; ky < 3; ky++)
#pragma unroll
                            for (int kx = 0; kx < 3; kx++)
                                s = fmaf(wv[ky * 3 + kx], xv[nt + ky][q + kx], s);
                        acc[g][nt][part * 2 + q] = s;
                    }
                }
            }
        }
    }

    // ---- LSTM epilogue -----------------------------------------------------
#pragma unroll
    for (int part = 0; part < 2; part++) {
        const int hid = hb * 16 + gq + part * 8;
        const bool hv = (hid < HID);
        float bi = 0.f, bfv = 0.f, bo = 0.f, bg = 0.f;
        if (hv) {
            bi = bias[hid]; bfv = bias[HID + hid];
            bo = bias[2 * HID + hid]; bg = bias[3 * HID + hid];
        }
#pragma unroll
        for (int nt = 0; nt < 4; nt++) {
            const int y = y0 + nt;
            const size_t coff =
                ((size_t)(b * HID + (hv ? hid : 0))) * 4096 + (size_t)y * 64 + xpx;
            float2 c2 = hv ? *(const float2*)(cbuf + coff) : make_float2(0.f, 0.f);
            float cold[2] = {c2.x, c2.y}, hn[2];
#pragma unroll
            for (int q = 0; q < 2; q++) {
                float I = sigf(acc[0][nt][part * 2 + q] + bi);
                float F = sigf(acc[1][nt][part * 2 + q] + bfv);
                float O = sigf(acc[2][nt][part * 2 + q] + bo);
                float G = tanh_fast(acc[3][nt][part * 2 + q] + bg);
                float cn = F * cold[q] + I * G;
                cold[q] = cn;
                hn[q] = O * tanh_fast(cn);
            }
            if (hv) {
                *(float2*)(cbuf + coff) = make_float2(cold[0], cold[1]);
                if (hfout)
                    *(float2*)(hfout + coff) = make_float2(hn[0], hn[1]);
            }
            // pack channel pairs: partner hid^1 lives at lane^4
            float pn0 = __shfl_xor_sync(0xffffffffu, hn[0], 4);
            float pn1 = __shfl_xor_sync(0xffffffffu, hn[1], 4);
            if (((gq & 1) == 0) && hv) {
                const int qp = hid >> 1;
                const size_t ob =
                    ((size_t)b * (HID / 2) + qp) * 4096 + (size_t)y * 64 + xpx;
                *(uint2*)(hout + ob) =
                    make_uint2(pack_hf(hn[0], pn0), pack_hf(hn[1], pn1));
            }
        }
    }
}

// -------------------- host driver -------------------------------------------
extern "C" void kernel_launch(void* const* d_in, const int* in_sizes, int n_in,
                              void* d_out, int out_size) {
    (void)in_sizes; (void)n_in; (void)out_size;
    const float* history = (const float*)d_in[0];
    const float* W0 = (const float*)d_in[2];
    const float* b0 = (const float*)d_in[3];
    const float* W1 = (const float*)d_in[4];
    const float* b1 = (const float*)d_in[5];

    uint32_t *h0p, *h1p, *wp0, *wp1;
    float *xf, *c0, *c1, *h1f, *wxt;
    cudaGetSymbolAddress((void**)&h0p, g_h0p);
    cudaGetSymbolAddress((void**)&h1p, g_h1p);
    cudaGetSymbolAddress((void**)&xf,  g_xf);
    cudaGetSymbolAddress((void**)&wp0, g_wp0);
    cudaGetSymbolAddress((void**)&wp1, g_wp1);
    cudaGetSymbolAddress((void**)&c0,  g_c0);
    cudaGetSymbolAddress((void**)&c1,  g_c1);
    cudaGetSymbolAddress((void**)&h1f, g_h1f);
    cudaGetSymbolAddress((void**)&wxt, g_wx);

    // lazily-created side stream + events (created on the first, uncaptured
    // correctness call; only their USE is captured into the graph)
    static cudaStream_t s2 = nullptr;
    static cudaEvent_t evP = nullptr, ev0[TSTEPS], ev1[TSTEPS];
    if (s2 == nullptr) {
        cudaStreamCreateWithFlags(&s2, cudaStreamNonBlocking);
        cudaEventCreateWithFlags(&evP, cudaEventDisableTiming);
        for (int t = 0; t < TSTEPS; t++) {
            cudaEventCreateWithFlags(&ev0[t], cudaEventDisableTiming);
            cudaEventCreateWithFlags(&ev1[t], cudaEventDisableTiming);
        }
    }

    zero_init_kernel<<<1024, 256>>>();
    xprep_kernel<<<768, 256>>>(history);
    repack_w<<<288, 256>>>(W0, wp0, 128, 129, 8, 8, 0);
    repack_w<<<41, 256>>>(W1, wp1, 12, 140, 1, 9, 1);
    repack_wx<<<18, 256>>>(W0, wxt);
    cudaEventRecord(evP, 0);
    cudaStreamWaitEvent(s2, evP, 0);

    const size_t H0SZ = (size_t)16 * 64 * 4096;
    const size_t H1SZ = (size_t)16 * 6 * 4096;

    int pa = 0;
    for (int t = 0; t < TSTEPS; t++) {
        const uint32_t* h0r = h0p + (size_t)pa * H0SZ;
        uint32_t*       h0w = h0p + (size_t)(1 - pa) * H0SZ;
        const uint32_t* h1r = h1p + (size_t)pa * H1SZ;
        uint32_t*       h1w = h1p + (size_t)(1 - pa) * H1SZ;

        // L0(t) overwrites h0 buffer 'pa' ... which L1(t-2) read: guard.
        if (t >= 2) cudaStreamWaitEvent(0, ev1[t - 2], 0);

        conv_step<64, 0, 8, 1, 128><<<dim3(16, 8, 16), 256, SMEM_BYTES>>>(
            h0r, nullptr, wp0, b0, xf + (size_t)t * 16 * 4096, wxt,
            c0, h0w, nullptr);
        cudaEventRecord(ev0[t], 0);

        // L1(t) on side stream: depends only on L0(t) + L1(t-1); overlaps L0(t+1)
        cudaStreamWaitEvent(s2, ev0[t], 0);
        conv_step<64, 6, 9, 0, 12><<<dim3(16, 1, 16), 256, SMEM_BYTES, s2>>>(
            h0w, h1r, wp1, b1, nullptr, nullptr,
            c1, h1w, (t == TSTEPS - 1) ? h1f : nullptr);
        cudaEventRecord(ev1[t], s2);

        pa ^= 1;
    }

    cudaStreamWaitEvent(0, ev1[TSTEPS - 1], 0);
    cudaMemcpyAsync(d_out, h1f, (size_t)16 * 12 * 4096 * sizeof(float),
                    cudaMemcpyDeviceToDevice);
}

// round 17
// speedup vs baseline: 6.6000x; 1.0170x over previous
#include <cuda_runtime.h>
#include <cuda_fp16.h>
#include <math.h>
#include <stdint.h>

// ---------------------------------------------------------------------------
// ConvLSTM (2 layers, 12 steps) — tensor-core implicit GEMM, pure fp16.
// R17: L1 M-packed (ch = hid*4+gate -> 3 exact m16 tiles, 12 MMAs/tap vs 16),
//      smem-transpose LSTM epilogue for L1; prologue streamed + trimmed zeroing.
//      L0 conv_step identical to R14 (known 2964.8us baseline).
// ---------------------------------------------------------------------------

#define TSTEPS 12

__device__ uint32_t g_h0p[2u * 16u * 64u * 4096u];   // h0 pair planes (fp16x2)
__device__ uint32_t g_h1p[2u * 16u * 6u  * 4096u];   // h1 pair planes
__device__ float    g_xf [12u * 16u * 4096u];        // x float planes per t
__device__ float    g_c0 [16u * 128u * 4096u];
__device__ float    g_c1 [16u * 12u  * 4096u];
__device__ float    g_h1f[16u * 12u * 4096u];        // float h1 (output, t=11)
__device__ uint32_t g_wp0[8u * 8u * 4608u];          // L0 frag-packed weights
__device__ uint32_t g_wp1[9u * 3456u];               // L1 packed-M weights
__device__ float    g_wx [128u * 36u];               // x weights [hid][g][tap]

#define SW_ACT   3520u              // one act chunk: 8 planes * 440 words
#define SW_XS    (2u * SW_ACT)
#define SMEM_L0  ((2u * SW_ACT + 400u) * 4u)         // 29,760 B
#define SMEM_L1  ((2u * SW_ACT) * 4u + 48u * 257u * 4u)  // 77,504 B

// -------------------- helpers ----------------------------------------------
__device__ __forceinline__ void mma_f16(float* d, const uint32_t* a,
                                        uint32_t b0, uint32_t b1) {
    asm volatile(
        "mma.sync.aligned.m16n8k16.row.col.f32.f16.f16.f32 "
        "{%0,%1,%2,%3}, {%4,%5,%6,%7}, {%8,%9}, {%0,%1,%2,%3};"
        : "+f"(d[0]), "+f"(d[1]), "+f"(d[2]), "+f"(d[3])
        : "r"(a[0]), "r"(a[1]), "r"(a[2]), "r"(a[3]), "r"(b0), "r"(b1));
}
__device__ __forceinline__ uint32_t smaddr(const void* p) {
    return (uint32_t)__cvta_generic_to_shared(p);
}
__device__ __forceinline__ void cpa16(uint32_t d, const void* s) {
    asm volatile("cp.async.cg.shared.global [%0], [%1], 16;" :: "r"(d), "l"(s));
}
__device__ __forceinline__ uint32_t pack_hf(float a, float b) {
    __half2 h = __floats2half2_rn(a, b); return *(uint32_t*)&h;
}
__device__ __forceinline__ float ex2f(float x){float y;asm("ex2.approx.f32 %0,%1;":"=f"(y):"f"(x));return y;}
__device__ __forceinline__ float rcpf(float x){float y;asm("rcp.approx.f32 %0,%1;":"=f"(y):"f"(x));return y;}
__device__ __forceinline__ float sigf(float x){return rcpf(1.f+ex2f(-1.44269504f*x));}
__device__ __forceinline__ float tanh_fast(float x){return 2.f*rcpf(1.f+ex2f(-2.88539008f*x))-1.f;}

// -------------------- init kernels -----------------------------------------
// Zero only buffers read before first write: h0p buf0, h1p buf0, c0, c1.
__global__ void zero_init_kernel() {
    size_t tid = (size_t)blockIdx.x * blockDim.x + threadIdx.x;
    size_t st  = (size_t)gridDim.x * blockDim.x;
    const size_t nh0 = (size_t)16 * 64 * 4096;   // buf0 only
    const size_t nh1 = (size_t)16 * 6 * 4096;    // buf0 only
    const size_t nc0 = (size_t)16 * 128 * 4096;
    const size_t nc1 = (size_t)16 * 12 * 4096;
    for (size_t i = tid; i < nh0; i += st) g_h0p[i] = 0u;
    for (size_t i = tid; i < nh1; i += st) g_h1p[i] = 0u;
    for (size_t i = tid; i < nc0; i += st) g_c0[i] = 0.f;
    for (size_t i = tid; i < nc1; i += st) g_c1[i] = 0.f;
}

__global__ void xprep_kernel(const float* __restrict__ hist) {
    int n = TSTEPS * 16 * 4096;
    for (int i = blockIdx.x * blockDim.x + threadIdx.x; i < n;
         i += gridDim.x * blockDim.x) {
        int px = i & 4095, b = (i >> 12) & 15, t = i >> 16;
        g_xf[((size_t)t * 16 + b) * 4096 + px] =
            hist[((size_t)b * TSTEPS + t) * 4096 + px];
    }
}

__global__ void repack_wx(const float* __restrict__ W, float* __restrict__ WX) {
    int idx = blockIdx.x * blockDim.x + threadIdx.x;
    if (idx < 128 * 36) {
        int hid = idx / 36, rem = idx % 36;
        int g = rem / 9, t = rem % 9;
        WX[idx] = W[((size_t)(g * 128 + hid) * 129 + 0) * 9 + t];
    }
}

// L0 weights -> A-fragment order: [hb][chunk][ (tap*4+g)*128 + lane*4 + r ]
__global__ void repack_w0(const float* __restrict__ W, uint32_t* __restrict__ Wp) {
    int total = 8 * 8 * 4608;
    for (int idx = blockIdx.x * blockDim.x + threadIdx.x; idx < total;
         idx += gridDim.x * blockDim.x) {
        int wrd = idx % 4608, rest = idx / 4608;
        int c = rest % 8, hb = rest / 8;
        int r = wrd & 3, lane = (wrd >> 2) & 31, gt = wrd >> 7;
        int g = gt & 3, t = gt >> 2;
        int m  = (lane >> 2) + (r & 1) * 8;
        int pr = (lane & 3) + ((r >> 1) & 1) * 4;
        int p  = c * 8 + pr;
        int hid = hb * 16 + m;
        int k0 = 2 * p + 1, k1 = 2 * p + 2;     // h0 pairs (cin 1..128)
        float w0 = W[((size_t)(g * 128 + hid) * 129 + k0) * 9 + t];
        float w1 = W[((size_t)(g * 128 + hid) * 129 + k1) * 9 + t];
        Wp[idx] = pack_hf(w0, w1);
    }
}

// L1 weights, packed-M: ch = hid*4+g, M=48 = 3 m16 tiles.
// Wp[c][ (t*3+mt)*128 + lane*4 + r ]
__global__ void repack_w1p(const float* __restrict__ W, uint32_t* __restrict__ Wp) {
    int total = 9 * 27 * 128;
    for (int idx = blockIdx.x * blockDim.x + threadIdx.x; idx < total;
         idx += gridDim.x * blockDim.x) {
        int wrd = idx % 128, rest = idx / 128;
        int tm = rest % 27, c = rest / 27;
        int t = tm / 3, mt = tm % 3;
        int r = wrd & 3, lane = wrd >> 2;
        int ml = (lane >> 2) + (r & 1) * 8;
        int pr = (lane & 3) + ((r >> 1) & 1) * 4;
        int p  = c * 8 + pr;
        int ch = mt * 16 + ml;
        int hid = ch >> 2, g = ch & 3;
        int k0 = -1, k1 = -1;
        if (p < 64)      { k0 = 2 * p; k1 = 2 * p + 1; }
        else if (p < 70) { k0 = 128 + 2 * (p - 64); k1 = k0 + 1; }
        float w0 = 0.f, w1 = 0.f;
        if (k0 >= 0 && k0 < 140) w0 = W[((size_t)(g * 12 + hid) * 140 + k0) * 9 + t];
        if (k1 >= 0 && k1 < 140) w1 = W[((size_t)(g * 12 + hid) * 140 + k1) * 9 + t];
        Wp[idx] = pack_hf(w0, w1);
    }
}

// -------------------- L0: conv + LSTM (R14, unchanged) ----------------------
__global__ __launch_bounds__(256, 2)
void conv_l0(const uint32_t* __restrict__ actA,    // h0 pair planes [b][64][4096]
             const uint32_t* __restrict__ Wg,      // [hb][8][4608]
             const float*    __restrict__ bias,
             const float*    __restrict__ xplane,  // [b][4096]
             const float*    __restrict__ wxt,     // [hid][4][9]
             float*          __restrict__ cbuf,
             uint32_t*       __restrict__ hout) {
    extern __shared__ uint32_t sm[];
    float* xs = (float*)(sm + SW_XS);
    const int tid = threadIdx.x;
    const int lane = tid & 31, warp = tid >> 5;
    const int tg = lane & 3, gq = lane >> 2;
    const int wx = warp;
    const int y0 = blockIdx.x * 4;
    const int hb = blockIdx.y;
    const int b  = blockIdx.z;
    const uint32_t* wgm = Wg + (size_t)hb * 8 * 4608 + lane * 4;

    if (tid < 192) {
        int side = tid & 1, v = tid >> 1;
        int r = v % 6, p = (v / 6) & 7, bfi = v / 48;
        uint32_t* dst = sm + bfi * SW_ACT + p * 440 + r * 72 + (side ? 68 : 0);
        *(uint4*)dst = make_uint4(0, 0, 0, 0);
    }
    {
        const float* xb = xplane + (size_t)b * 4096;
        for (int u = tid; u < 396; u += 256) {
            int r = u / 66, cc = u - r * 66;
            int gy = y0 + r - 1, gx = cc - 1;
            float v = 0.f;
            if ((unsigned)gy < 64u && (unsigned)gx < 64u) v = xb[gy * 64 + gx];
            xs[u] = v;
        }
    }

    float acc[4][4][4];
#pragma unroll
    for (int g = 0; g < 4; g++)
#pragma unroll
        for (int n = 0; n < 4; n++)
#pragma unroll
            for (int r = 0; r < 4; r++) acc[g][n][r] = 0.f;

    auto ldchunk = [&](int c, int bfi) {
#pragma unroll
        for (int k = 0; k < 3; k++) {
            int u = tid + k * 256;
            int p = u & 7, rest = u >> 3;
            int r = rest % 6, seg = rest / 6;
            int pair = c * 8 + p;
            int y = y0 + r - 1;
            uint32_t* dst = sm + bfi * SW_ACT + p * 440 + r * 72 + 4 + seg * 4;
            const uint32_t* src = nullptr;
            if ((unsigned)y < 64u)
                src = actA + ((size_t)b * 64 + pair) * 4096 + y * 64 + seg * 4;
            if (src) cpa16(smaddr(dst), src);
            else     *(uint4*)dst = make_uint4(0, 0, 0, 0);
        }
        asm volatile("cp.async.commit_group;");
    };

    ldchunk(0, 0);
    for (int c = 0; c < 8; c++) {
        const int bfi = c & 1;
        if (c + 1 < 8) { ldchunk(c + 1, bfi ^ 1); asm volatile("cp.async.wait_group 1;"); }
        else           { asm volatile("cp.async.wait_group 0;"); }
        __syncthreads();
        const uint32_t* aB = sm + bfi * SW_ACT;
        const uint32_t* wc = wgm + (size_t)c * 4608;
#pragma unroll
        for (int ky = 0; ky < 3; ky++)
#pragma unroll
        for (int kx = 0; kx < 3; kx++) {
            const int t = ky * 3 + kx;
            const int cb = 4 + wx * 8 + gq + kx - 1;
            uint4 ah[4];
#pragma unroll
            for (int g = 0; g < 4; g++)
                ah[g] = __ldg((const uint4*)(wc + (t * 4 + g) * 128));
            uint32_t bh[4][2];
#pragma unroll
            for (int nt = 0; nt < 4; nt++) {
                int o0 = tg * 440 + (ky + nt) * 72 + cb;
                bh[nt][0] = aB[o0]; bh[nt][1] = aB[o0 + 4 * 440];
            }
#pragma unroll
            for (int g = 0; g < 4; g++)
#pragma unroll
                for (int nt = 0; nt < 4; nt++)
                    mma_f16(acc[g][nt], (const uint32_t*)&ah[g], bh[nt][0], bh[nt][1]);
        }
        __syncthreads();
    }

    const int xpx = wx * 8 + tg * 2;
    // x-channel scalar taps (fma pipe)
    {
        float xv[6][4];
#pragma unroll
        for (int r = 0; r < 6; r++)
#pragma unroll
            for (int j = 0; j < 4; j++) xv[r][j] = xs[r * 66 + xpx + j];
#pragma unroll
        for (int part = 0; part < 2; part++) {
            const int hid = hb * 16 + gq + part * 8;
            const float* wrow = wxt + (size_t)hid * 36;
#pragma unroll
            for (int g = 0; g < 4; g++) {
                float wv[9];
#pragma unroll
                for (int t9 = 0; t9 < 9; t9++) wv[t9] = __ldg(wrow + g * 9 + t9);
#pragma unroll
                for (int nt = 0; nt < 4; nt++)
#pragma unroll
                    for (int q = 0; q < 2; q++) {
                        float s = acc[g][nt][part * 2 + q];
#pragma unroll
                        for (int ky = 0; ky < 3; ky++)
#pragma unroll
                            for (int kx = 0; kx < 3; kx++)
                                s = fmaf(wv[ky * 3 + kx], xv[nt + ky][q + kx], s);
                        acc[g][nt][part * 2 + q] = s;
                    }
            }
        }
    }
    // LSTM epilogue
#pragma unroll
    for (int part = 0; part < 2; part++) {
        const int hid = hb * 16 + gq + part * 8;
        const float bi = bias[hid], bfv = bias[128 + hid];
        const float bo = bias[256 + hid], bg = bias[384 + hid];
#pragma unroll
        for (int nt = 0; nt < 4; nt++) {
            const int y = y0 + nt;
            const size_t coff = ((size_t)(b * 128 + hid)) * 4096 + (size_t)y * 64 + xpx;
            float2 c2 = *(const float2*)(cbuf + coff);
            float cold[2] = {c2.x, c2.y}, hn[2];
#pragma unroll
            for (int q = 0; q < 2; q++) {
                float I = sigf(acc[0][nt][part * 2 + q] + bi);
                float F = sigf(acc[1][nt][part * 2 + q] + bfv);
                float O = sigf(acc[2][nt][part * 2 + q] + bo);
                float G = tanh_fast(acc[3][nt][part * 2 + q] + bg);
                float cn = F * cold[q] + I * G;
                cold[q] = cn;
                hn[q] = O * tanh_fast(cn);
            }
            *(float2*)(cbuf + coff) = make_float2(cold[0], cold[1]);
            float pn0 = __shfl_xor_sync(0xffffffffu, hn[0], 4);
            float pn1 = __shfl_xor_sync(0xffffffffu, hn[1], 4);
            if ((gq & 1) == 0) {
                const size_t ob = ((size_t)b * 64 + (hid >> 1)) * 4096 + (size_t)y * 64 + xpx;
                *(uint2*)(g_h0p + 0) // placeholder avoided; real write below
                    ;
                *(uint2*)(hout + ob) = make_uint2(pack_hf(hn[0], pn0), pack_hf(hn[1], pn1));
            }
        }
    }
}

// -------------------- L1: packed-M conv + LSTM ------------------------------
// Warp: 3 m-tiles (ch=hid*4+g, M=48) x 32 px. 48 f32 accs/thread.
__global__ __launch_bounds__(256, 2)
void conv_l1p(const uint32_t* __restrict__ actA,   // h0 pair planes
              const uint32_t* __restrict__ actB,   // h1 pair planes
              const uint32_t* __restrict__ Wg,     // [9][3456]
              const float*    __restrict__ bias,
              float*          __restrict__ cbuf,
              uint32_t*       __restrict__ hout,
              float*          __restrict__ hfout) {
    extern __shared__ uint32_t sm[];
    float* stg = (float*)(sm + 2 * SW_ACT);        // [48][257]
    const int tid = threadIdx.x;
    const int lane = tid & 31, warp = tid >> 5;
    const int tg = lane & 3, gq = lane >> 2;
    const int wx = warp;
    const int y0 = blockIdx.x * 4;
    const int b  = blockIdx.z;
    const uint32_t* wgm = Wg + lane * 4;

    if (tid < 192) {
        int side = tid & 1, v = tid >> 1;
        int r = v % 6, p = (v / 6) & 7, bfi = v / 48;
        uint32_t* dst = sm + bfi * SW_ACT + p * 440 + r * 72 + (side ? 68 : 0);
        *(uint4*)dst = make_uint4(0, 0, 0, 0);
    }

    float acc[3][4][4];
#pragma unroll
    for (int mt = 0; mt < 3; mt++)
#pragma unroll
        for (int n = 0; n < 4; n++)
#pragma unroll
            for (int r = 0; r < 4; r++) acc[mt][n][r] = 0.f;

    auto ldchunk = [&](int c, int bfi) {
#pragma unroll
        for (int k = 0; k < 3; k++) {
            int u = tid + k * 256;
            int p = u & 7, rest = u >> 3;
            int r = rest % 6, seg = rest / 6;
            int pair = c * 8 + p;
            int y = y0 + r - 1;
            uint32_t* dst = sm + bfi * SW_ACT + p * 440 + r * 72 + 4 + seg * 4;
            const uint32_t* src = nullptr;
            if ((unsigned)y < 64u) {
                if (pair < 64)
                    src = actA + ((size_t)b * 64 + pair) * 4096 + y * 64 + seg * 4;
                else if (pair < 70)
                    src = actB + ((size_t)b * 6 + (pair - 64)) * 4096 + y * 64 + seg * 4;
            }
            if (src) cpa16(smaddr(dst), src);
            else     *(uint4*)dst = make_uint4(0, 0, 0, 0);
        }
        asm volatile("cp.async.commit_group;");
    };

    ldchunk(0, 0);
    for (int c = 0; c < 9; c++) {
        const int bfi = c & 1;
        if (c + 1 < 9) { ldchunk(c + 1, bfi ^ 1); asm volatile("cp.async.wait_group 1;"); }
        else           { asm volatile("cp.async.wait_group 0;"); }
        __syncthreads();
        const uint32_t* aB = sm + bfi * SW_ACT;
        const uint32_t* wc = wgm + (size_t)c * 3456;
#pragma unroll
        for (int ky = 0; ky < 3; ky++)
#pragma unroll
        for (int kx = 0; kx < 3; kx++) {
            const int t = ky * 3 + kx;
            const int cb = 4 + wx * 8 + gq + kx - 1;
            uint4 ah[3];
#pragma unroll
            for (int mt = 0; mt < 3; mt++)
                ah[mt] = __ldg((const uint4*)(wc + (t * 3 + mt) * 128));
            uint32_t bh[4][2];
#pragma unroll
            for (int nt = 0; nt < 4; nt++) {
                int o0 = tg * 440 + (ky + nt) * 72 + cb;
                bh[nt][0] = aB[o0]; bh[nt][1] = aB[o0 + 4 * 440];
            }
#pragma unroll
            for (int mt = 0; mt < 3; mt++)
#pragma unroll
                for (int nt = 0; nt < 4; nt++)
                    mma_f16(acc[mt][nt], (const uint32_t*)&ah[mt], bh[nt][0], bh[nt][1]);
        }
        __syncthreads();
    }

    // stage D to smem: stg[ch][nt*64+x]
#pragma unroll
    for (int mt = 0; mt < 3; mt++)
#pragma unroll
        for (int nt = 0; nt < 4; nt++)
#pragma unroll
            for (int r = 0; r < 4; r++) {
                int part = r >> 1, q = r & 1;
                int ch = mt * 16 + gq + part * 8;
                int x  = wx * 8 + tg * 2 + q;
                stg[ch * 257 + nt * 64 + x] = acc[mt][nt][r];
            }
    __syncthreads();

    // consumer: one pixel per thread, all 12 hid
    {
        const int y = y0 + (tid >> 6), x = tid & 63;
        float hnv[12];
#pragma unroll
        for (int h = 0; h < 12; h++) {
            float I = stg[(4 * h + 0) * 257 + tid] + __ldg(bias + h);
            float F = stg[(4 * h + 1) * 257 + tid] + __ldg(bias + 12 + h);
            float O = stg[(4 * h + 2) * 257 + tid] + __ldg(bias + 24 + h);
            float G = stg[(4 * h + 3) * 257 + tid] + __ldg(bias + 36 + h);
            const size_t ci = ((size_t)(b * 12 + h)) * 4096 + (size_t)y * 64 + x;
            float cn = sigf(F) * cbuf[ci] + sigf(I) * tanh_fast(G);
            cbuf[ci] = cn;
            float hn = sigf(O) * tanh_fast(cn);
            hnv[h] = hn;
            if (hfout) hfout[ci] = hn;
        }
#pragma unroll
        for (int qp = 0; qp < 6; qp++)
            hout[((size_t)b * 6 + qp) * 4096 + (size_t)y * 64 + x] =
                pack_hf(hnv[2 * qp], hnv[2 * qp + 1]);
    }
}

// -------------------- host driver -------------------------------------------
extern "C" void kernel_launch(void* const* d_in, const int* in_sizes, int n_in,
                              void* d_out, int out_size) {
    (void)in_sizes; (void)n_in; (void)out_size;
    const float* history = (const float*)d_in[0];
    const float* W0 = (const float*)d_in[2];
    const float* b0 = (const float*)d_in[3];
    const float* W1 = (const float*)d_in[4];
    const float* b1 = (const float*)d_in[5];

    uint32_t *h0p, *h1p, *wp0, *wp1;
    float *xf, *c0, *c1, *h1f, *wxt;
    cudaGetSymbolAddress((void**)&h0p, g_h0p);
    cudaGetSymbolAddress((void**)&h1p, g_h1p);
    cudaGetSymbolAddress((void**)&xf,  g_xf);
    cudaGetSymbolAddress((void**)&wp0, g_wp0);
    cudaGetSymbolAddress((void**)&wp1, g_wp1);
    cudaGetSymbolAddress((void**)&c0,  g_c0);
    cudaGetSymbolAddress((void**)&c1,  g_c1);
    cudaGetSymbolAddress((void**)&h1f, g_h1f);
    cudaGetSymbolAddress((void**)&wxt, g_wx);

    static cudaStream_t s2 = nullptr;
    static cudaEvent_t evO = nullptr, evR = nullptr, ev0[TSTEPS], ev1[TSTEPS];
    if (s2 == nullptr) {
        cudaStreamCreateWithFlags(&s2, cudaStreamNonBlocking);
        cudaEventCreateWithFlags(&evO, cudaEventDisableTiming);
        cudaEventCreateWithFlags(&evR, cudaEventDisableTiming);
        for (int t = 0; t < TSTEPS; t++) {
            cudaEventCreateWithFlags(&ev0[t], cudaEventDisableTiming);
            cudaEventCreateWithFlags(&ev1[t], cudaEventDisableTiming);
        }
        cudaFuncSetAttribute(conv_l1p, cudaFuncAttributeMaxDynamicSharedMemorySize,
                             SMEM_L1);
    }

    // prologue: repacks on s2 concurrently with zero/xprep on main
    cudaEventRecord(evO, 0);
    cudaStreamWaitEvent(s2, evO, 0);
    repack_w0<<<288, 256, 0, s2>>>(W0, wp0);
    repack_w1p<<<122, 256, 0, s2>>>(W1, wp1);
    repack_wx<<<18, 256, 0, s2>>>(W0, wxt);
    cudaEventRecord(evR, s2);
    zero_init_kernel<<<1024, 256>>>();
    xprep_kernel<<<768, 256>>>(history);
    cudaStreamWaitEvent(0, evR, 0);

    const size_t H0SZ = (size_t)16 * 64 * 4096;
    const size_t H1SZ = (size_t)16 * 6 * 4096;

    int pa = 0;
    for (int t = 0; t < TSTEPS; t++) {
        const uint32_t* h0r = h0p + (size_t)pa * H0SZ;
        uint32_t*       h0w = h0p + (size_t)(1 - pa) * H0SZ;
        const uint32_t* h1r = h1p + (size_t)pa * H1SZ;
        uint32_t*       h1w = h1p + (size_t)(1 - pa) * H1SZ;

        if (t >= 2) cudaStreamWaitEvent(0, ev1[t - 2], 0);

        conv_l0<<<dim3(16, 8, 16), 256, SMEM_L0>>>(
            h0r, wp0, b0, xf + (size_t)t * 16 * 4096, wxt, c0, h0w);
        cudaEventRecord(ev0[t], 0);

        cudaStreamWaitEvent(s2, ev0[t], 0);
        conv_l1p<<<dim3(16, 1, 16), 256, SMEM_L1, s2>>>(
            h0w, h1r, wp1, b1, c1, h1w, (t == TSTEPS - 1) ? h1f : nullptr);
        cudaEventRecord(ev1[t], s2);

        pa ^= 1;
    }

    cudaStreamWaitEvent(0, ev1[TSTEPS - 1], 0);
    cudaMemcpyAsync(d_out, h1f, (size_t)16 * 12 * 4096 * sizeof(float),
                    cudaMemcpyDeviceToDevice);
}